// round 13
// baseline (speedup 1.0000x reference)
#include <cuda_runtime.h>

#define BATCH 64
#define SEQ   512
#define DIN   256
#define UNITS 512

#define NCTA    128
#define N_BG    16       // batch groups
#define N_UG    8        // unit groups
#define BPG     4        // batches per CTA
#define UPG     64       // columns per CTA
#define THREADS 512

// Ping-pong recurrent state. Per bg block: 512 cols * 4 batches = 2048 floats.
// Layout (pair-interleaved for f32x2): float idx = (c>>1)*8 + b*2 + (c&1).
__device__ float4   g_h[2][N_BG][UNITS * BPG / 4];
__device__ unsigned g_flag[NCTA * 32];   // per-(bg,ug) producer step counters
__device__ unsigned g_gbar;              // monotone grid barrier (never reset)

__device__ __forceinline__ void ffma2(unsigned long long& d,
                                      unsigned long long a,
                                      unsigned long long b) {
    asm("fma.rn.f32x2 %0, %1, %2, %0;" : "+l"(d) : "l"(a), "l"(b));
}

__device__ __forceinline__ unsigned ld_acq(const unsigned* p) {
    unsigned v;
    asm volatile("ld.acquire.gpu.global.u32 %0, [%1];" : "=r"(v) : "l"(p) : "memory");
    return v;
}

__global__ __launch_bounds__(THREADS, 1) void fused_kernel(
    const float* __restrict__ X, const float* __restrict__ Tm,
    const float* __restrict__ Bm, const float* __restrict__ bias,
    const float* __restrict__ h0, float* __restrict__ out)
{
    extern __shared__ char sm[];
    const int tid = threadIdx.x;
    const int cta = blockIdx.x;
    const int bg  = cta >> 3;
    const int ug  = cta & 7;

    // ---- Phase A0: reset own flag, write own h0 chunk ------------------
    if (tid == 0) g_flag[cta * 32] = 0u;
    if (tid < 256) {
        int b = tid >> 6, cc = tid & 63;
        ((float*)&g_h[0][bg][0])[ug * 256 + (cc >> 1) * 8 + b * 2 + (cc & 1)]
            = h0[ug * 64 + cc];
    }

    // ---- Phase A1: GEMM  xT -> out[t][b][u] ----------------------------
    // 512 threads = two half-blocks, each doing an independent 64x64 tile.
    {
        float*  Ts  = (float*)sm;                               // 64 KB resident
        const int half = tid >> 8;
        const int htid = tid & 255;
        float2* Xs2 = (float2*)(sm + 65536) + half * 4096;      // 2 stages x 2048

        const int tx = htid & 15, ty = htid >> 4;
        const int col0 = ug * 64;

#pragma unroll
        for (int i = 0; i < 8; i++) {             // T slice, loaded once
            int j = tid + i * 512;
            int k = j >> 4, c4 = j & 15;
            *(float4*)&Ts[k * 64 + c4 * 4] =
                *(const float4*)(Tm + (size_t)k * UNITS + col0 + c4 * 4);
        }
        __syncthreads();

        for (int q = 0; q < 16; q++) {
            const int row0 = ((cta >> 3) + 16 * (2 * q + half)) * 64;

            // preload k-chunk 0 into stage 0
#pragma unroll
            for (int p = 0; p < 2; p++) {
                int j = htid + p * 256;
                int r = j >> 3, c4 = j & 7;
                float4 v = *(const float4*)(X + (size_t)(row0 + r) * DIN + c4 * 4);
                float2* d = Xs2 + r * 32 + c4 * 4;
                d[0] = make_float2(v.x, v.x); d[1] = make_float2(v.y, v.y);
                d[2] = make_float2(v.z, v.z); d[3] = make_float2(v.w, v.w);
            }
            __syncthreads();

            unsigned long long acc2[4][2];
#pragma unroll
            for (int i = 0; i < 4; i++) { acc2[i][0] = 0ull; acc2[i][1] = 0ull; }

            for (int kc = 0; kc < 8; kc++) {
                float4 nv[2];
                if (kc < 7) {
#pragma unroll
                    for (int p = 0; p < 2; p++) {
                        int j = htid + p * 256;
                        int r = j >> 3, c4 = j & 7;
                        nv[p] = *(const float4*)(X + (size_t)(row0 + r) * DIN
                                                   + (kc + 1) * 32 + c4 * 4);
                    }
                }
                const float2* Xc = Xs2 + (kc & 1) * 2048;
#pragma unroll
                for (int kk = 0; kk < 32; kk++) {
                    unsigned long long a0 = *(const unsigned long long*)&Xc[(ty * 4 + 0) * 32 + kk];
                    unsigned long long a1 = *(const unsigned long long*)&Xc[(ty * 4 + 1) * 32 + kk];
                    unsigned long long a2 = *(const unsigned long long*)&Xc[(ty * 4 + 2) * 32 + kk];
                    unsigned long long a3 = *(const unsigned long long*)&Xc[(ty * 4 + 3) * 32 + kk];
                    ulonglong2 bb = *(const ulonglong2*)&Ts[(kc * 32 + kk) * 64 + tx * 4];
                    ffma2(acc2[0][0], a0, bb.x); ffma2(acc2[0][1], a0, bb.y);
                    ffma2(acc2[1][0], a1, bb.x); ffma2(acc2[1][1], a1, bb.y);
                    ffma2(acc2[2][0], a2, bb.x); ffma2(acc2[2][1], a2, bb.y);
                    ffma2(acc2[3][0], a3, bb.x); ffma2(acc2[3][1], a3, bb.y);
                }
                if (kc < 7) {
                    float2* d = Xs2 + ((kc + 1) & 1) * 2048;
#pragma unroll
                    for (int p = 0; p < 2; p++) {
                        int j = htid + p * 256;
                        int r = j >> 3, c4 = j & 7;
                        float2* dd = d + r * 32 + c4 * 4;
                        dd[0] = make_float2(nv[p].x, nv[p].x);
                        dd[1] = make_float2(nv[p].y, nv[p].y);
                        dd[2] = make_float2(nv[p].z, nv[p].z);
                        dd[3] = make_float2(nv[p].w, nv[p].w);
                    }
                }
                __syncthreads();
            }

#pragma unroll
            for (int i = 0; i < 4; i++) {         // scatter to [t][b][u]
                int r = row0 + ty * 4 + i;
                int t = r & (SEQ - 1);
                int b = r >> 9;
                union { float4 f4; unsigned long long u2[2]; } o;
                o.u2[0] = acc2[i][0]; o.u2[1] = acc2[i][1];
                *(float4*)(out + ((size_t)(t * BATCH + b)) * UNITS + col0 + tx * 4) = o.f4;
            }
        }
    }

    // ---- grid barrier (monotone, +128 per launch) ----------------------
    __syncthreads();
    if (tid == 0) {
        unsigned old;
        asm volatile("atom.release.gpu.global.add.u32 %0, [%1], 1;"
                     : "=r"(old) : "l"(&g_gbar) : "memory");
        unsigned target = (old & ~(unsigned)(NCTA - 1)) + NCTA;
        while (ld_acq(&g_gbar) < target) { }
    }
    __syncthreads();

    // ---- Phase B: recurrence scan (16 warps, 32-k chunks) --------------
    {
        float* hs  = (float*)sm;             // 2 x 2048 floats (parity dbuf)
        float* red = (float*)(sm + 16384);   // 256 x 17 floats split-K partials

        const int u  = tid & 31;
        const int w  = tid >> 5;             // warp id == k-chunk (16 x 32)
        const int c0 = ug * 64 + u;          // this thread's two B columns
        const int k0 = w * 32;
        const bool own = ((w >> 1) == ug);   // chunk produced by this CTA

        // B slice in registers: 2 cols x 16 packed k-pairs
        unsigned long long w2a[16], w2b[16];
#pragma unroll
        for (int j = 0; j < 16; j++) {
            float2 p0 = make_float2(__ldg(Bm + (size_t)(k0 + 2 * j) * UNITS + c0),
                                    __ldg(Bm + (size_t)(k0 + 2 * j + 1) * UNITS + c0));
            float2 p1 = make_float2(__ldg(Bm + (size_t)(k0 + 2 * j) * UNITS + c0 + 32),
                                    __ldg(Bm + (size_t)(k0 + 2 * j + 1) * UNITS + c0 + 32));
            w2a[j] = *(unsigned long long*)&p0;
            w2b[j] = *(unsigned long long*)&p1;
        }

        const int bo = (tid & 255) >> 6;     // epilogue ownership (tid<256)
        const int co = tid & 63;
        const int cg = ug * 64 + co;
        const float bv = bias[cg];
        const size_t obase = (size_t)(bg * BPG + bo) * UNITS + cg;
        const int hidx = (cg >> 1) * 8 + bo * 2 + (cg & 1);
        unsigned* consFlag = &g_flag[(bg * 8 + (w >> 1)) * 32];
        unsigned* prodFlag = &g_flag[cta * 32];
        float* hb0 = (float*)&g_h[0][bg][0];
        float* hb1 = (float*)&g_h[1][bg][0];

        for (int t = 0; t < SEQ; t++) {
            const size_t oidx = (size_t)t * (BATCH * UNITS) + obase;
            float xt = (tid < 256) ? __ldcg(out + oidx) : 0.0f;   // prefetch

            // per-warp wait on the single producer of this warp's k-chunk
            if (t > 0 && !own) { while (ld_acq(consFlag) < (unsigned)t) { } }

            const float* hsrc = (t & 1) ? hb1 : hb0;
            float*       hdst = (t & 1) ? hb0 : hb1;
            float*       hsC  = hs + (t & 1) * 2048;
            float*       hsN  = hs + ((t + 1) & 1) * 2048;

            // stage own 512B chunk (32k x 4b) unless epilogue already put it here
            if (t == 0 || !own) {
                ((float4*)hsC)[k0 + u] = __ldcg((const float4*)hsrc + k0 + u);
            }
            __syncwarp();

            unsigned long long a0=0,a1=0,a2=0,a3=0,a4=0,a5=0,a6=0,a7=0;
            const ulonglong2* hp = (const ulonglong2*)hsC + w * 32;
#pragma unroll
            for (int j = 0; j < 16; j++) {
                ulonglong2 v0 = hp[2 * j];          // batches 0,1 (k-pair packed)
                ulonglong2 v1 = hp[2 * j + 1];      // batches 2,3
                ffma2(a0, v0.x, w2a[j]); ffma2(a1, v0.y, w2a[j]);
                ffma2(a2, v1.x, w2a[j]); ffma2(a3, v1.y, w2a[j]);
                ffma2(a4, v0.x, w2b[j]); ffma2(a5, v0.y, w2b[j]);
                ffma2(a6, v1.x, w2b[j]); ffma2(a7, v1.y, w2b[j]);
            }
            {   // split-K partials, 17-padded (conflict-free: gcd(17,32)=1)
                float2 f;
                f = *(float2*)&a0; red[(0 * 64 + u) * 17 + w] = f.x + f.y;
                f = *(float2*)&a1; red[(1 * 64 + u) * 17 + w] = f.x + f.y;
                f = *(float2*)&a2; red[(2 * 64 + u) * 17 + w] = f.x + f.y;
                f = *(float2*)&a3; red[(3 * 64 + u) * 17 + w] = f.x + f.y;
                f = *(float2*)&a4; red[(0 * 64 + u + 32) * 17 + w] = f.x + f.y;
                f = *(float2*)&a5; red[(1 * 64 + u + 32) * 17 + w] = f.x + f.y;
                f = *(float2*)&a6; red[(2 * 64 + u + 32) * 17 + w] = f.x + f.y;
                f = *(float2*)&a7; red[(3 * 64 + u + 32) * 17 + w] = f.x + f.y;
            }
            __syncthreads();

            if (tid < 256) {
                float s = 0.0f;
                const float* rp = red + tid * 17;
#pragma unroll
                for (int k = 0; k < 16; k++) s += rp[k];

                // modrelu: sign(z) * relu(|z| + bias), sign(0) = 0
                float z = xt + s;
                float m = fabsf(z) + bv;
                float h = (z == 0.0f) ? 0.0f : copysignf(fmaxf(m, 0.0f), z);

                __stcg(hdst + hidx, h);     // publish next state (L2)
                hsN[hidx] = h;              // own-chunk fast path for next step
                out[oidx] = h;              // state output
            }
            __syncthreads();                // stores issued before release
            if (tid == 0)
                asm volatile("red.release.gpu.global.add.u32 [%0], 1;"
                             :: "l"(prodFlag) : "memory");
        }
    }
}

// ---------------------------------------------------------------------------
extern "C" void kernel_launch(void* const* d_in, const int* in_sizes, int n_in,
                              void* d_out, int out_size) {
    const float* x    = (const float*)d_in[0];
    const float* T    = (const float*)d_in[1];
    const float* B    = (const float*)d_in[2];
    const float* bias = (const float*)d_in[3];
    const float* h0   = (const float*)d_in[4];
    if (in_sizes[1] == UNITS * UNITS && in_sizes[2] == DIN * UNITS) {
        const float* tmp = T; T = B; B = tmp;
    }
    float* out = (float*)d_out;

    const int smem = 65536 + 65536;   // T slice + 2 half-block X double buffers
    cudaFuncSetAttribute(fused_kernel,
                         cudaFuncAttributeMaxDynamicSharedMemorySize, smem);
    fused_kernel<<<NCTA, THREADS, smem>>>(x, T, B, bias, h0, out);
}

// round 17
// speedup vs baseline: 1.3450x; 1.3450x over previous
#include <cuda_runtime.h>

#define BATCH 64
#define SEQ   512
#define DIN   256
#define UNITS 512

#define NCTA    128
#define N_BG    16       // batch groups
#define N_UG    8        // unit groups
#define BPG     4        // batches per CTA
#define UPG     64       // columns per CTA
#define THREADS 256

// Ping-pong recurrent state. Per bg block: 512 cols * 4 batches = 2048 floats.
// Layout (pair-interleaved for f32x2): float idx = (c>>1)*8 + b*2 + (c&1).
__device__ float4   g_h[2][N_BG][UNITS * BPG / 4];
__device__ unsigned g_flag[NCTA * 32];   // per-(bg,ug) producer counters (8/step)
__device__ unsigned g_gbar;              // monotone grid barrier (never reset)

__device__ __forceinline__ void ffma2(unsigned long long& d,
                                      unsigned long long a,
                                      unsigned long long b) {
    asm("fma.rn.f32x2 %0, %1, %2, %0;" : "+l"(d) : "l"(a), "l"(b));
}

__device__ __forceinline__ unsigned ld_acq(const unsigned* p) {
    unsigned v;
    asm volatile("ld.acquire.gpu.global.u32 %0, [%1];" : "=r"(v) : "l"(p) : "memory");
    return v;
}

__global__ __launch_bounds__(THREADS, 1) void fused_kernel(
    const float* __restrict__ X, const float* __restrict__ Tm,
    const float* __restrict__ Bm, const float* __restrict__ bias,
    const float* __restrict__ h0, float* __restrict__ out)
{
    extern __shared__ char sm[];
    const int tid = threadIdx.x;
    const int cta = blockIdx.x;
    const int bg  = cta >> 3;
    const int ug  = cta & 7;

    // ---- Phase A0: reset own flag, write own h0 chunk ------------------
    if (tid == 0) g_flag[cta * 32] = 0u;
    {
        int b = tid >> 6, cc = tid & 63;
        ((float*)&g_h[0][bg][0])[ug * 256 + (cc >> 1) * 8 + b * 2 + (cc & 1)]
            = h0[ug * 64 + cc];
    }

    // ---- Phase A1: GEMM  xT -> out[t][b][u]  (R8-proven) ---------------
    {
        float*  Ts  = (float*)sm;                 // [256][64]   64 KB (resident)
        float2* Xs2 = (float2*)(sm + 65536);      // 2 x [64][32] dup-pairs, 32 KB

        const int tx = tid & 15, ty = tid >> 4;
        const int col0 = ug * 64;

#pragma unroll
        for (int i = 0; i < 16; i++) {            // T slice, loaded once
            int j = tid + i * 256;
            int k = j >> 4, c4 = j & 15;
            *(float4*)&Ts[k * 64 + c4 * 4] =
                *(const float4*)(Tm + (size_t)k * UNITS + col0 + c4 * 4);
        }
        __syncthreads();

        for (int q = 0; q < 32; q++) {
            const int row0 = ((cta >> 3) + 16 * q) * 64;

#pragma unroll
            for (int p = 0; p < 2; p++) {         // preload k-chunk 0
                int j = tid + p * 256;
                int r = j >> 3, c4 = j & 7;
                float4 v = *(const float4*)(X + (size_t)(row0 + r) * DIN + c4 * 4);
                float2* d = Xs2 + r * 32 + c4 * 4;
                d[0] = make_float2(v.x, v.x); d[1] = make_float2(v.y, v.y);
                d[2] = make_float2(v.z, v.z); d[3] = make_float2(v.w, v.w);
            }
            __syncthreads();

            unsigned long long acc2[4][2];
#pragma unroll
            for (int i = 0; i < 4; i++) { acc2[i][0] = 0ull; acc2[i][1] = 0ull; }

            for (int kc = 0; kc < 8; kc++) {
                float4 nv[2];
                if (kc < 7) {
#pragma unroll
                    for (int p = 0; p < 2; p++) {
                        int j = tid + p * 256;
                        int r = j >> 3, c4 = j & 7;
                        nv[p] = *(const float4*)(X + (size_t)(row0 + r) * DIN
                                                   + (kc + 1) * 32 + c4 * 4);
                    }
                }
                const float2* Xc = Xs2 + (kc & 1) * 2048;
#pragma unroll
                for (int kk = 0; kk < 32; kk++) {
                    unsigned long long a0 = *(const unsigned long long*)&Xc[(ty * 4 + 0) * 32 + kk];
                    unsigned long long a1 = *(const unsigned long long*)&Xc[(ty * 4 + 1) * 32 + kk];
                    unsigned long long a2 = *(const unsigned long long*)&Xc[(ty * 4 + 2) * 32 + kk];
                    unsigned long long a3 = *(const unsigned long long*)&Xc[(ty * 4 + 3) * 32 + kk];
                    ulonglong2 bb = *(const ulonglong2*)&Ts[(kc * 32 + kk) * 64 + tx * 4];
                    ffma2(acc2[0][0], a0, bb.x); ffma2(acc2[0][1], a0, bb.y);
                    ffma2(acc2[1][0], a1, bb.x); ffma2(acc2[1][1], a1, bb.y);
                    ffma2(acc2[2][0], a2, bb.x); ffma2(acc2[2][1], a2, bb.y);
                    ffma2(acc2[3][0], a3, bb.x); ffma2(acc2[3][1], a3, bb.y);
                }
                if (kc < 7) {
                    float2* d = Xs2 + ((kc + 1) & 1) * 2048;
#pragma unroll
                    for (int p = 0; p < 2; p++) {
                        int j = tid + p * 256;
                        int r = j >> 3, c4 = j & 7;
                        float2* dd = d + r * 32 + c4 * 4;
                        dd[0] = make_float2(nv[p].x, nv[p].x);
                        dd[1] = make_float2(nv[p].y, nv[p].y);
                        dd[2] = make_float2(nv[p].z, nv[p].z);
                        dd[3] = make_float2(nv[p].w, nv[p].w);
                    }
                }
                __syncthreads();
            }

#pragma unroll
            for (int i = 0; i < 4; i++) {         // scatter to [t][b][u]
                int r = row0 + ty * 4 + i;
                int t = r & (SEQ - 1);
                int b = r >> 9;
                union { float4 f4; unsigned long long u2[2]; } o;
                o.u2[0] = acc2[i][0]; o.u2[1] = acc2[i][1];
                *(float4*)(out + ((size_t)(t * BATCH + b)) * UNITS + col0 + tx * 4) = o.f4;
            }
        }
    }

    // ---- grid barrier (monotone, +128 per launch) ----------------------
    __syncthreads();
    if (tid == 0) {
        unsigned old;
        asm volatile("atom.release.gpu.global.add.u32 %0, [%1], 1;"
                     : "=r"(old) : "l"(&g_gbar) : "memory");
        unsigned target = (old & ~(unsigned)(NCTA - 1)) + NCTA;
        while (ld_acq(&g_gbar) < target) { }
    }
    __syncthreads();

    // ---- Phase B: recurrence scan (8 warps, 64-k chunks) ---------------
    // One __syncthreads per step. Per-warp release-publish; red[] parity
    // double buffer makes the removed end-of-step barrier safe.
    {
        float* hs  = (float*)sm;            // 2048 floats staged h (8 KB)
        float* red = (float*)(sm + 8192);   // 2 x 2304 floats split-K partials

        const int u  = tid & 31;
        const int kc = tid >> 5;            // warp id == k-chunk == producer ug
        const int c0 = ug * 64 + u;         // this thread's two B columns
        const int k0 = kc * 64;

        // B slice in registers: 2 cols x 32 packed k-pairs
        unsigned long long w2a[32], w2b[32];
#pragma unroll
        for (int j = 0; j < 32; j++) {
            float2 p0 = make_float2(__ldg(Bm + (size_t)(k0 + 2 * j) * UNITS + c0),
                                    __ldg(Bm + (size_t)(k0 + 2 * j + 1) * UNITS + c0));
            float2 p1 = make_float2(__ldg(Bm + (size_t)(k0 + 2 * j) * UNITS + c0 + 32),
                                    __ldg(Bm + (size_t)(k0 + 2 * j + 1) * UNITS + c0 + 32));
            w2a[j] = *(unsigned long long*)&p0;
            w2b[j] = *(unsigned long long*)&p1;
        }

        const int bo = tid >> 6;            // epilogue (batch, col) ownership
        const int co = tid & 63;
        const float bv = bias[ug * 64 + co];
        const size_t obase = (size_t)(bg * BPG + bo) * UNITS + ug * 64 + co;
        const int hidx = ug * 256 + (co >> 1) * 8 + bo * 2 + (co & 1);
        unsigned* consFlag = &g_flag[(bg * 8 + kc) * 32];
        unsigned* prodFlag = &g_flag[cta * 32];
        float* hb0 = (float*)&g_h[0][bg][0];
        float* hb1 = (float*)&g_h[1][bg][0];

        for (int t = 0; t < SEQ; t++) {
            const size_t oidx = (size_t)t * (BATCH * UNITS) + obase;
            float xt = __ldcg(out + oidx);          // prefetch under the wait

            // per-warp wait: producer CTA done with step t-1 (8 warp arrivals)
            if (t > 0) {
                const unsigned tgt = 8u * (unsigned)t;
                while (ld_acq(consFlag) < tgt) { }
            }

            const float* hsrc = (t & 1) ? hb1 : hb0;
            float*       hdst = (t & 1) ? hb0 : hb1;
            float*       redC = red + (t & 1) * 2304;

            {   // stage own 1 KB chunk (64k x 4b), warp-local
                const float4* s4 = (const float4*)hsrc + kc * 64;
                float4* d4 = (float4*)hs + kc * 64;
                d4[u]      = __ldcg(s4 + u);
                d4[u + 32] = __ldcg(s4 + u + 32);
            }
            __syncwarp();

            unsigned long long a0=0,a1=0,a2=0,a3=0,a4=0,a5=0,a6=0,a7=0;
            const ulonglong2* hp = (const ulonglong2*)hs + kc * 64;
#pragma unroll
            for (int j = 0; j < 32; j++) {
                ulonglong2 v0 = hp[2 * j];          // batches 0,1 (k-pair packed)
                ulonglong2 v1 = hp[2 * j + 1];      // batches 2,3
                ffma2(a0, v0.x, w2a[j]); ffma2(a1, v0.y, w2a[j]);
                ffma2(a2, v1.x, w2a[j]); ffma2(a3, v1.y, w2a[j]);
                ffma2(a4, v0.x, w2b[j]); ffma2(a5, v0.y, w2b[j]);
                ffma2(a6, v1.x, w2b[j]); ffma2(a7, v1.y, w2b[j]);
            }
            {   // split-K partials, 9-padded (9 coprime 32 -> conflict-free)
                float2 f;
                f = *(float2*)&a0; redC[(0 * 64 + u) * 9 + kc] = f.x + f.y;
                f = *(float2*)&a1; redC[(1 * 64 + u) * 9 + kc] = f.x + f.y;
                f = *(float2*)&a2; redC[(2 * 64 + u) * 9 + kc] = f.x + f.y;
                f = *(float2*)&a3; redC[(3 * 64 + u) * 9 + kc] = f.x + f.y;
                f = *(float2*)&a4; redC[(0 * 64 + u + 32) * 9 + kc] = f.x + f.y;
                f = *(float2*)&a5; redC[(1 * 64 + u + 32) * 9 + kc] = f.x + f.y;
                f = *(float2*)&a6; redC[(2 * 64 + u + 32) * 9 + kc] = f.x + f.y;
                f = *(float2*)&a7; redC[(3 * 64 + u + 32) * 9 + kc] = f.x + f.y;
            }
            __syncthreads();                        // the ONLY sync per step

            // epilogue: reduce 8 partials, modrelu, publish per-warp
            float s = 0.0f;
            {
                const float* rp = redC + tid * 9;
#pragma unroll
                for (int k = 0; k < 8; k++) s += rp[k];
            }

            float z = xt + s;
            float m = fabsf(z) + bv;
            float h = (z == 0.0f) ? 0.0f : copysignf(fmaxf(m, 0.0f), z);

            __stcg(hdst + hidx, h);                 // publish next state (L2)
            asm volatile("membar.gl;" ::: "memory");  // order warp's stores
            if (u == 0)                             // lane0 of each warp arrives
                asm volatile("red.release.gpu.global.add.u32 [%0], 1;"
                             :: "l"(prodFlag) : "memory");
            out[oidx] = h;                          // off the publish path
        }
    }
}

// ---------------------------------------------------------------------------
extern "C" void kernel_launch(void* const* d_in, const int* in_sizes, int n_in,
                              void* d_out, int out_size) {
    const float* x    = (const float*)d_in[0];
    const float* T    = (const float*)d_in[1];
    const float* B    = (const float*)d_in[2];
    const float* bias = (const float*)d_in[3];
    const float* h0   = (const float*)d_in[4];
    if (in_sizes[1] == UNITS * UNITS && in_sizes[2] == DIN * UNITS) {
        const float* tmp = T; T = B; B = tmp;
    }
    float* out = (float*)d_out;

    const int smem = 65536 + 32768;   // 96 KB: T slice + X double buffer / scan
    cudaFuncSetAttribute(fused_kernel,
                         cudaFuncAttributeMaxDynamicSharedMemorySize, smem);
    fused_kernel<<<NCTA, THREADS, smem>>>(x, T, B, bias, h0, out);
}